// round 3
// baseline (speedup 1.0000x reference)
#include <cuda_runtime.h>
#include <math.h>
#include <stdint.h>

#define BATCH 16
#define SEQ   4096
#define DIM   256
#define FEPS  1e-6f

// ---------------- scratch (device globals; allocation-free rule) ----------------
__device__ __align__(256) float g_phi_q[BATCH * SEQ * DIM];   // 64 MB
__device__ __align__(256) float g_phi_k[BATCH * SEQ * DIM];   // 64 MB
__device__ __align__(256) float g_Vb[BATCH * SEQ * DIM];      // 64 MB
__device__ __align__(256) float g_KV[BATCH * DIM * DIM];      // 4 MB
__device__ __align__(256) float g_colsum[BATCH * DIM];
__device__ __align__(256) float g_rowfac[BATCH * SEQ];
__device__ __align__(256) float g_pm[BATCH * 32 * DIM];
__device__ __align__(256) float g_pl[BATCH * 32 * DIM];
__device__ __align__(256) float g_m[BATCH * DIM];
__device__ __align__(256) float g_il[BATCH * DIM];

__device__ __forceinline__ float fast_sigmoid(float x) {
    return __fdividef(1.f, 1.f + __expf(-x));
}

// ---------------- zero init for atomics targets ----------------
__global__ void zero_kernel() {
    unsigned i = blockIdx.x * blockDim.x + threadIdx.x;
    if (i < BATCH * DIM * DIM) g_KV[i] = 0.f;
    if (i < BATCH * DIM) g_colsum[i] = 0.f;
}

// ---------------- 128x128x16 SGEMM, 8x8 per thread ----------------
// MODE 0: C = sigmoid(A@B + bias)        (aux = bias[DIM])
// MODE 1: C = rowfac[row] * (A@B)        (aux = rowfac, per-z stride auxStrideZ)
template <int MODE>
__global__ __launch_bounds__(256) void gemm128_kernel(
    const float* __restrict__ A, const float* __restrict__ B,
    const float* __restrict__ aux, float* __restrict__ C,
    size_t strideAz, size_t strideBz, size_t strideCz, int auxStrideZ)
{
    const int K = DIM, LDB = DIM, LDC = DIM;
    int z = blockIdx.z;
    const float* Ab = A + (size_t)z * strideAz + (size_t)blockIdx.x * 128 * K;
    const float* Bb = B + (size_t)z * strideBz + blockIdx.y * 128;
    float* Cb = C + (size_t)z * strideCz;

    __shared__ float As[16][132];   // A transposed tile, padded
    __shared__ float Bs[16][128];

    int tid = threadIdx.x;
    int tx = tid & 15, ty = tid >> 4;

    float acc[8][8] = {};

    for (int kt = 0; kt < K; kt += 16) {
#pragma unroll
        for (int i = 0; i < 2; i++) {
            int lin = tid + i * 256;
            // A: 128 rows x 16 k  (512 float4)
            int rowA = lin >> 2, c4 = lin & 3;
            float4 va = *(const float4*)(Ab + (size_t)rowA * K + kt + c4 * 4);
            As[c4 * 4 + 0][rowA] = va.x;
            As[c4 * 4 + 1][rowA] = va.y;
            As[c4 * 4 + 2][rowA] = va.z;
            As[c4 * 4 + 3][rowA] = va.w;
            // B: 16 k x 128 cols (512 float4)
            int rowB = lin >> 5, cB = (lin & 31) * 4;
            *(float4*)&Bs[rowB][cB] =
                *(const float4*)(Bb + (size_t)(kt + rowB) * LDB + cB);
        }
        __syncthreads();
#pragma unroll
        for (int k = 0; k < 16; k++) {
            float4 a0 = *(float4*)&As[k][ty * 8];
            float4 a1 = *(float4*)&As[k][ty * 8 + 4];
            float4 b0 = *(float4*)&Bs[k][tx * 8];
            float4 b1 = *(float4*)&Bs[k][tx * 8 + 4];
            float a[8] = {a0.x, a0.y, a0.z, a0.w, a1.x, a1.y, a1.z, a1.w};
            float b[8] = {b0.x, b0.y, b0.z, b0.w, b1.x, b1.y, b1.z, b1.w};
#pragma unroll
            for (int i = 0; i < 8; i++)
#pragma unroll
                for (int j = 0; j < 8; j++)
                    acc[i][j] = fmaf(a[i], b[j], acc[i][j]);
        }
        __syncthreads();
    }

    int col0 = blockIdx.y * 128 + tx * 8;
    float4 bias0, bias1;
    if (MODE == 0) {
        bias0 = *(const float4*)&aux[col0];
        bias1 = *(const float4*)&aux[col0 + 4];
    }
#pragma unroll
    for (int i = 0; i < 8; i++) {
        int row = blockIdx.x * 128 + ty * 8 + i;
        float4 o0, o1;
        if (MODE == 0) {
            o0.x = fast_sigmoid(acc[i][0] + bias0.x);
            o0.y = fast_sigmoid(acc[i][1] + bias0.y);
            o0.z = fast_sigmoid(acc[i][2] + bias0.z);
            o0.w = fast_sigmoid(acc[i][3] + bias0.w);
            o1.x = fast_sigmoid(acc[i][4] + bias1.x);
            o1.y = fast_sigmoid(acc[i][5] + bias1.y);
            o1.z = fast_sigmoid(acc[i][6] + bias1.z);
            o1.w = fast_sigmoid(acc[i][7] + bias1.w);
        } else {
            float f = aux[(size_t)z * auxStrideZ + row];
            o0.x = f * acc[i][0]; o0.y = f * acc[i][1];
            o0.z = f * acc[i][2]; o0.w = f * acc[i][3];
            o1.x = f * acc[i][4]; o1.y = f * acc[i][5];
            o1.z = f * acc[i][6]; o1.w = f * acc[i][7];
        }
        *(float4*)(Cb + (size_t)row * LDC + col0) = o0;
        *(float4*)(Cb + (size_t)row * LDC + col0 + 4) = o1;
    }
}

// ---------------- rowsum of phi_q -> combined gate/normalizer factor ----------------
__global__ void rowfac_kernel() {
    int warp = threadIdx.x >> 5, lane = threadIdx.x & 31;
    size_t row = (size_t)blockIdx.x * 8 + warp;   // < BATCH*SEQ
    const float* p = g_phi_q + row * DIM;
    float4 v0 = *(const float4*)&p[lane * 4];
    float4 v1 = *(const float4*)&p[128 + lane * 4];
    float s = v0.x + v0.y + v0.z + v0.w + v1.x + v1.y + v1.z + v1.w;
#pragma unroll
    for (int off = 16; off; off >>= 1) s += __shfl_xor_sync(0xffffffffu, s, off);
    if (lane == 0) {
        g_rowfac[row] = fast_sigmoid(s) * __fdividef(1.f, s + FEPS);
    }
}

// ---------------- column sums of phi_k over sequence ----------------
__global__ void colsum_kernel() {
    int b = blockIdx.x >> 5, ns = blockIdx.x & 31;
    const int CH = SEQ / 32;   // 128
    const float* p = g_phi_k + ((size_t)b * SEQ + (size_t)ns * CH) * DIM + threadIdx.x;
    float s = 0.f;
#pragma unroll 4
    for (int n = 0; n < CH; n++) s += p[(size_t)n * DIM];
    atomicAdd(&g_colsum[b * DIM + threadIdx.x], s);
}

// ---------------- per-column online softmax partials over sequence ----------------
__global__ void stats_kernel(const float* __restrict__ V) {
    int b = blockIdx.x >> 5, ns = blockIdx.x & 31;
    const int CH = SEQ / 32;
    int d = threadIdx.x;
    float inv = __fdividef(1.f, g_colsum[b * DIM + d] + FEPS);
    size_t base = ((size_t)b * SEQ + (size_t)ns * CH) * DIM + d;
    float m = -1e30f, l = 0.f;
    for (int n = 0; n < CH; n++) {
        float s = g_phi_k[base + (size_t)n * DIM] * inv * V[base + (size_t)n * DIM];
        float nm = fmaxf(m, s);
        l = l * __expf(m - nm) + __expf(s - nm);
        m = nm;
    }
    g_pm[(b * 32 + ns) * DIM + d] = m;
    g_pl[(b * 32 + ns) * DIM + d] = l;
}

__global__ void merge_kernel() {
    int b = blockIdx.x, d = threadIdx.x;
    float m = -1e30f;
#pragma unroll
    for (int c = 0; c < 32; c++) m = fmaxf(m, g_pm[(b * 32 + c) * DIM + d]);
    float l = 0.f;
#pragma unroll
    for (int c = 0; c < 32; c++)
        l += g_pl[(b * 32 + c) * DIM + d] * __expf(g_pm[(b * 32 + c) * DIM + d] - m);
    g_m[b * DIM + d] = m;
    g_il[b * DIM + d] = __fdividef(1.f, l);
}

// ---------------- V_b = softmax(O*V, axis=seq) ----------------
__global__ void vb_kernel(const float* __restrict__ V) {
    size_t idx = ((size_t)blockIdx.x * blockDim.x + threadIdx.x) * 4;
    int d = (int)(idx & (DIM - 1));
    int b = (int)(idx >> 20);                  // SEQ*DIM = 2^20
    int bd = b * DIM + d;
    float4 pk = *(const float4*)&g_phi_k[idx];
    float4 v  = *(const float4*)&V[idx];
    float4 cs = *(const float4*)&g_colsum[bd];
    float4 mm = *(const float4*)&g_m[bd];
    float4 il = *(const float4*)&g_il[bd];
    float4 o;
    o.x = __expf(pk.x * __fdividef(1.f, cs.x + FEPS) * v.x - mm.x) * il.x;
    o.y = __expf(pk.y * __fdividef(1.f, cs.y + FEPS) * v.y - mm.y) * il.y;
    o.z = __expf(pk.z * __fdividef(1.f, cs.z + FEPS) * v.z - mm.z) * il.z;
    o.w = __expf(pk.w * __fdividef(1.f, cs.w + FEPS) * v.w - mm.w) * il.w;
    *(float4*)&g_Vb[idx] = o;
}

// ---------------- KV[b] = phi_k[b]^T @ Vb[b], split-N with atomics ----------------
#define NSPLIT_KV 8
__global__ __launch_bounds__(256) void kv_kernel() {
    int b = blockIdx.z / NSPLIT_KV, ns = blockIdx.z % NSPLIT_KV;
    const int CH = SEQ / NSPLIT_KV;   // 512
    const float* Ab = g_phi_k + ((size_t)b * SEQ + (size_t)ns * CH) * DIM + blockIdx.x * 128;
    const float* Bb = g_Vb    + ((size_t)b * SEQ + (size_t)ns * CH) * DIM + blockIdx.y * 128;

    __shared__ float As[16][128];
    __shared__ float Bs[16][128];
    int tid = threadIdx.x;
    int tx = tid & 15, ty = tid >> 4;
    float acc[8][8] = {};

    for (int n0 = 0; n0 < CH; n0 += 16) {
#pragma unroll
        for (int i = 0; i < 2; i++) {
            int lin = tid + i * 256;
            int r = lin >> 5, c = (lin & 31) * 4;
            *(float4*)&As[r][c] = *(const float4*)(Ab + (size_t)(n0 + r) * DIM + c);
            *(float4*)&Bs[r][c] = *(const float4*)(Bb + (size_t)(n0 + r) * DIM + c);
        }
        __syncthreads();
#pragma unroll
        for (int k = 0; k < 16; k++) {
            float4 a0 = *(float4*)&As[k][ty * 8];
            float4 a1 = *(float4*)&As[k][ty * 8 + 4];
            float4 b0 = *(float4*)&Bs[k][tx * 8];
            float4 b1 = *(float4*)&Bs[k][tx * 8 + 4];
            float a[8] = {a0.x, a0.y, a0.z, a0.w, a1.x, a1.y, a1.z, a1.w};
            float bb[8] = {b0.x, b0.y, b0.z, b0.w, b1.x, b1.y, b1.z, b1.w};
#pragma unroll
            for (int i = 0; i < 8; i++)
#pragma unroll
                for (int j = 0; j < 8; j++)
                    acc[i][j] = fmaf(a[i], bb[j], acc[i][j]);
        }
        __syncthreads();
    }

    float* Cb = g_KV + (size_t)b * DIM * DIM;
    int d0 = blockIdx.x * 128 + ty * 8;
    int e0 = blockIdx.y * 128 + tx * 8;
#pragma unroll
    for (int i = 0; i < 8; i++)
#pragma unroll
        for (int j = 0; j < 8; j++)
            atomicAdd(&Cb[(size_t)(d0 + i) * DIM + e0 + j], acc[i][j]);
}

// ---------------- launch ----------------
extern "C" void kernel_launch(void* const* d_in, const int* in_sizes, int n_in,
                              void* d_out, int out_size) {
    const float* Q  = (const float*)d_in[0];
    const float* K  = (const float*)d_in[1];
    const float* V  = (const float*)d_in[2];
    const float* Wq = (const float*)d_in[3];
    const float* bq = (const float*)d_in[4];
    const float* Wk = (const float*)d_in[5];
    const float* bk = (const float*)d_in[6];
    float* out = (float*)d_out;

    void *p_phi_q, *p_phi_k, *p_KV, *p_rowfac;
    cudaGetSymbolAddress(&p_phi_q, g_phi_q);
    cudaGetSymbolAddress(&p_phi_k, g_phi_k);
    cudaGetSymbolAddress(&p_KV, g_KV);
    cudaGetSymbolAddress(&p_rowfac, g_rowfac);

    zero_kernel<<<4096, 256>>>();

    // phi_q = sigmoid(Q@Wq + bq), phi_k = sigmoid(K@Wk + bk)   [65536 x 256]
    gemm128_kernel<0><<<dim3(512, 2, 1), 256>>>(Q, Wq, bq, (float*)p_phi_q, 0, 0, 0, 0);
    gemm128_kernel<0><<<dim3(512, 2, 1), 256>>>(K, Wk, bk, (float*)p_phi_k, 0, 0, 0, 0);

    rowfac_kernel<<<BATCH * SEQ / 8, 256>>>();
    colsum_kernel<<<BATCH * 32, 256>>>();
    stats_kernel<<<BATCH * 32, 256>>>(V);
    merge_kernel<<<BATCH, 256>>>();
    vb_kernel<<<BATCH * SEQ * DIM / 4 / 256, 256>>>(V);

    kv_kernel<<<dim3(2, 2, BATCH * NSPLIT_KV), 256>>>();

    // R = rowfac * (phi_q @ KV)   per-batch GEMM [4096x256] @ [256x256]
    gemm128_kernel<1><<<dim3(SEQ / 128, 2, BATCH), 256>>>(
        (const float*)p_phi_q, (const float*)p_KV, (const float*)p_rowfac, out,
        (size_t)SEQ * DIM, (size_t)DIM * DIM, (size_t)SEQ * DIM, SEQ);
}

// round 9
// speedup vs baseline: 1.9344x; 1.9344x over previous
#include <cuda_runtime.h>
#include <cuda_bf16.h>
#include <mma.h>
#include <math.h>
#include <stdint.h>

using namespace nvcuda;

#define BATCH 16
#define SEQ   4096
#define DIM   256
#define FEPS  1e-6f

// ---------------- scratch ----------------
__device__ __align__(256) float g_KV[BATCH * DIM * DIM];
__device__ __align__(256) float g_colsum[BATCH * DIM];
__device__ __align__(256) float g_l[BATCH * DIM];
__device__ __align__(256) float g_rowfac[BATCH * SEQ];
__device__ __align__(256) __nv_bfloat16 g_Wq_hi[DIM * DIM];
__device__ __align__(256) __nv_bfloat16 g_Wq_lo[DIM * DIM];
__device__ __align__(256) __nv_bfloat16 g_Wk_hi[DIM * DIM];
__device__ __align__(256) __nv_bfloat16 g_Wk_lo[DIM * DIM];
__device__ __align__(256) __nv_bfloat16 g_pq_hi[BATCH * SEQ * DIM];
__device__ __align__(256) __nv_bfloat16 g_pq_lo[BATCH * SEQ * DIM];
__device__ __align__(256) __nv_bfloat16 g_pk_hi[BATCH * SEQ * DIM];
__device__ __align__(256) __nv_bfloat16 g_pk_lo[BATCH * SEQ * DIM];
__device__ __align__(256) __nv_bfloat16 g_E_hi[BATCH * SEQ * DIM];
__device__ __align__(256) __nv_bfloat16 g_E_lo[BATCH * SEQ * DIM];
__device__ __align__(256) __nv_bfloat16 g_KVs_hi[BATCH * DIM * DIM];
__device__ __align__(256) __nv_bfloat16 g_KVs_lo[BATCH * DIM * DIM];

__device__ __forceinline__ float fast_sigmoid(float x) {
    return __fdividef(1.f, 1.f + __expf(-x));
}
__device__ __forceinline__ float bf16_round(float a) {
    return __bfloat162float(__float2bfloat16(a));
}
__device__ __forceinline__ uint32_t pack_bf16(float a, float b) {
    __nv_bfloat162 h = __floats2bfloat162_rn(a, b);
    return (uint32_t)__bfloat16_as_ushort(h.x) | ((uint32_t)__bfloat16_as_ushort(h.y) << 16);
}
__device__ __forceinline__ float2 unpack_bf16(uint32_t u) {
    __nv_bfloat162 t;
    *reinterpret_cast<uint32_t*>(&t) = u;
    return make_float2(__bfloat162float(t.x), __bfloat162float(t.y));
}

// ---------------- zero init ----------------
__global__ void zero_kernel() {
    unsigned i = blockIdx.x * blockDim.x + threadIdx.x;
    if (i < BATCH * DIM * DIM) g_KV[i] = 0.f;
    if (i < BATCH * DIM) { g_colsum[i] = 0.f; g_l[i] = 0.f; }
}

// ---------------- W split (no transpose) ----------------
__global__ void wsplit_kernel(const float* __restrict__ Wq, const float* __restrict__ Wk) {
    const float* W = blockIdx.y ? Wk : Wq;
    __nv_bfloat16* oh = blockIdx.y ? g_Wk_hi : g_Wq_hi;
    __nv_bfloat16* ol = blockIdx.y ? g_Wk_lo : g_Wq_lo;
    int i = blockIdx.x * 256 + threadIdx.x;
    float x = W[i];
    oh[i] = __float2bfloat16(x);
    ol[i] = __float2bfloat16(x - bf16_round(x));
}

// ============ WMMA bf16-split GEMM: CTA tile 128x128, 8 warps (4m x 2n) ============
// MODE 0: write Chi/Clo = split(sigmoid(acc + bias[col]))
// MODE 1: C = rowfac[z*SEQ+row] * acc   (fp32 out)
// MODE 2: atomicAdd(C, acc)             (K-split)
// ASRC_F32: A is fp32 row-major (convert in-kernel), else bf16 hi/lo pair
// ATRANS:   A operand is K-major in memory: element (m,k) at A[k*256 + m]  (col_major frags)
template <int MODE, int ASRC_F32, int ATRANS>
__global__ __launch_bounds__(256) void wgemm(
    const void* Ap, const __nv_bfloat16* Alo,
    const __nv_bfloat16* Bhp, const __nv_bfloat16* Blp,
    const float* __restrict__ aux, float* C,
    __nv_bfloat16* Chi, __nv_bfloat16* Clo,
    int kchunks, int ksplit, int ksplitlen,
    long Az, long Bz, long Cz)
{
    __shared__ __align__(128) char smbuf[43008];
    __nv_bfloat16* sAh = (__nv_bfloat16*)smbuf;            // 6144 elems
    __nv_bfloat16* sAl = sAh + 6144;                       // 6144
    __nv_bfloat16* sBh = sAh + 12288;                      // 4608 (32x144)
    __nv_bfloat16* sBl = sAh + 16896;                      // 4608

    int tid = threadIdx.x;
    int wid = tid >> 5;
    int warp_m = wid & 3, warp_n = wid >> 2;
    int bm = blockIdx.x, bn = blockIdx.y;
    int z = blockIdx.z / ksplit;
    int k0base = (blockIdx.z % ksplit) * ksplitlen;

    wmma::fragment<wmma::accumulator, 16, 16, 16, float> acc[2][4];
#pragma unroll
    for (int i = 0; i < 2; i++)
#pragma unroll
        for (int j = 0; j < 4; j++) wmma::fill_fragment(acc[i][j], 0.f);

    for (int c = 0; c < kchunks; c++) {
        int k0 = k0base + c * 32;
        // ---- stage A ----
        if (ASRC_F32) {
            const float* A = (const float*)Ap;
#pragma unroll
            for (int i = 0; i < 4; i++) {
                int idx = tid + i * 256;
                int r = idx >> 3, c4 = (idx & 7) * 4;
                float4 v = *(const float4*)(A + (long)(bm * 128 + r) * 256 + k0 + c4);
                *(uint2*)&sAh[r * 48 + c4] = make_uint2(pack_bf16(v.x, v.y), pack_bf16(v.z, v.w));
                *(uint2*)&sAl[r * 48 + c4] = make_uint2(
                    pack_bf16(v.x - bf16_round(v.x), v.y - bf16_round(v.y)),
                    pack_bf16(v.z - bf16_round(v.z), v.w - bf16_round(v.w)));
            }
        } else if (!ATRANS) {
            const __nv_bfloat16* Ah = (const __nv_bfloat16*)Ap;
#pragma unroll
            for (int i = 0; i < 2; i++) {
                int idx = tid + i * 256;
                int r = idx >> 2, c8 = (idx & 3) * 8;
                long src = z * Az + (long)(bm * 128 + r) * 256 + k0 + c8;
                *(uint4*)&sAh[r * 48 + c8] = *(const uint4*)(Ah + src);
                *(uint4*)&sAl[r * 48 + c8] = *(const uint4*)(Alo + src);
            }
        } else {
            const __nv_bfloat16* Ah = (const __nv_bfloat16*)Ap;
#pragma unroll
            for (int i = 0; i < 2; i++) {
                int idx = tid + i * 256;
                int r = idx >> 4, c8 = (idx & 15) * 8;
                long src = z * Az + (long)(k0 + r) * 256 + bm * 128 + c8;
                *(uint4*)&sAh[r * 144 + c8] = *(const uint4*)(Ah + src);
                *(uint4*)&sAl[r * 144 + c8] = *(const uint4*)(Alo + src);
            }
        }
        // ---- stage B (always bf16 pair, row-major [K][256]) ----
#pragma unroll
        for (int i = 0; i < 2; i++) {
            int idx = tid + i * 256;
            int r = idx >> 4, c8 = (idx & 15) * 8;
            long src = z * Bz + (long)(k0 + r) * 256 + bn * 128 + c8;
            *(uint4*)&sBh[r * 144 + c8] = *(const uint4*)(Bhp + src);
            *(uint4*)&sBl[r * 144 + c8] = *(const uint4*)(Blp + src);
        }
        __syncthreads();

#pragma unroll
        for (int kk = 0; kk < 32; kk += 16) {
            wmma::fragment<wmma::matrix_b, 16, 16, 16, __nv_bfloat16, wmma::row_major> bh[4], bl[4];
#pragma unroll
            for (int j = 0; j < 4; j++) {
                int n0 = warp_n * 64 + j * 16;
                wmma::load_matrix_sync(bh[j], &sBh[kk * 144 + n0], 144);
                wmma::load_matrix_sync(bl[j], &sBl[kk * 144 + n0], 144);
            }
            if (ATRANS) {
                wmma::fragment<wmma::matrix_a, 16, 16, 16, __nv_bfloat16, wmma::col_major> ah[2], al[2];
#pragma unroll
                for (int i = 0; i < 2; i++) {
                    int m0 = warp_m * 32 + i * 16;
                    wmma::load_matrix_sync(ah[i], &sAh[kk * 144 + m0], 144);
                    wmma::load_matrix_sync(al[i], &sAl[kk * 144 + m0], 144);
                }
#pragma unroll
                for (int i = 0; i < 2; i++)
#pragma unroll
                    for (int j = 0; j < 4; j++) {
                        wmma::mma_sync(acc[i][j], ah[i], bh[j], acc[i][j]);
                        wmma::mma_sync(acc[i][j], al[i], bh[j], acc[i][j]);
                        wmma::mma_sync(acc[i][j], ah[i], bl[j], acc[i][j]);
                    }
            } else {
                wmma::fragment<wmma::matrix_a, 16, 16, 16, __nv_bfloat16, wmma::row_major> ah[2], al[2];
#pragma unroll
                for (int i = 0; i < 2; i++) {
                    int m0 = warp_m * 32 + i * 16;
                    wmma::load_matrix_sync(ah[i], &sAh[m0 * 48 + kk], 48);
                    wmma::load_matrix_sync(al[i], &sAl[m0 * 48 + kk], 48);
                }
#pragma unroll
                for (int i = 0; i < 2; i++)
#pragma unroll
                    for (int j = 0; j < 4; j++) {
                        wmma::mma_sync(acc[i][j], ah[i], bh[j], acc[i][j]);
                        wmma::mma_sync(acc[i][j], al[i], bh[j], acc[i][j]);
                        wmma::mma_sync(acc[i][j], ah[i], bl[j], acc[i][j]);
                    }
            }
        }
        __syncthreads();
    }

    // ---- epilogue via fp32 staging (reuses smbuf), two 64-col halves ----
    float* stage = (float*)smbuf;
#pragma unroll
    for (int h = 0; h < 2; h++) {
        if (warp_n == h) {
#pragma unroll
            for (int i = 0; i < 2; i++)
#pragma unroll
                for (int j = 0; j < 4; j++)
                    wmma::store_matrix_sync(&stage[(warp_m * 32 + i * 16) * 72 + j * 16],
                                            acc[i][j], 72, wmma::mem_row_major);
        }
        __syncthreads();
        int r = tid >> 1, c0 = (tid & 1) * 32;
        int colg = bn * 128 + h * 64 + c0;
        long row_g = (long)bm * 128 + r;
        float v[32];
#pragma unroll
        for (int j = 0; j < 32; j++) v[j] = stage[r * 72 + c0 + j];
        if (MODE == 0) {
            long off = row_g * 256 + colg;
            uint32_t ph[16], pl[16];
#pragma unroll
            for (int p = 0; p < 16; p++) {
                float a = fast_sigmoid(v[2 * p] + aux[colg + 2 * p]);
                float b = fast_sigmoid(v[2 * p + 1] + aux[colg + 2 * p + 1]);
                ph[p] = pack_bf16(a, b);
                pl[p] = pack_bf16(a - bf16_round(a), b - bf16_round(b));
            }
#pragma unroll
            for (int p = 0; p < 16; p += 4) {
                *(uint4*)(Chi + off + 2 * p) = make_uint4(ph[p], ph[p + 1], ph[p + 2], ph[p + 3]);
                *(uint4*)(Clo + off + 2 * p) = make_uint4(pl[p], pl[p + 1], pl[p + 2], pl[p + 3]);
            }
        } else if (MODE == 1) {
            float f = aux[(long)z * SEQ + row_g];
            long off = z * Cz + row_g * 256 + colg;
#pragma unroll
            for (int j = 0; j < 32; j += 4)
                *(float4*)(C + off + j) = make_float4(f * v[j], f * v[j + 1], f * v[j + 2], f * v[j + 3]);
        } else {
            long off = z * Cz + row_g * 256 + colg;
#pragma unroll
            for (int j = 0; j < 32; j++) atomicAdd(C + off + j, v[j]);
        }
        __syncthreads();
    }
}

// ---------------- rowfac: sigmoid(rowsum)/(rowsum+eps) from pq hi/lo ----------------
__global__ void rowfac_kernel() {
    int warp = threadIdx.x >> 5, lane = threadIdx.x & 31;
    long row = (long)blockIdx.x * 8 + warp;
    long base = row * 256 + lane * 8;
    uint4 h = *(const uint4*)(g_pq_hi + base);
    uint4 l = *(const uint4*)(g_pq_lo + base);
    float s = 0.f;
    uint32_t hu[4] = {h.x, h.y, h.z, h.w}, lu[4] = {l.x, l.y, l.z, l.w};
#pragma unroll
    for (int p = 0; p < 4; p++) {
        float2 a = unpack_bf16(hu[p]), b = unpack_bf16(lu[p]);
        s += a.x + a.y + b.x + b.y;
    }
#pragma unroll
    for (int off = 16; off; off >>= 1) s += __shfl_xor_sync(0xffffffffu, s, off);
    if (lane == 0) g_rowfac[row] = fast_sigmoid(s) * __fdividef(1.f, s + FEPS);
}

// ---------------- colsum of phi_k over sequence ----------------
__global__ void colsum_kernel() {
    int b = blockIdx.x >> 5, ns = blockIdx.x & 31;
    long base = ((long)b * SEQ + (long)ns * 128) * 256 + threadIdx.x;
    float s = 0.f;
#pragma unroll 4
    for (int n = 0; n < 128; n++) {
        long o = base + (long)n * 256;
        s += __bfloat162float(g_pk_hi[o]) + __bfloat162float(g_pk_lo[o]);
    }
    atomicAdd(&g_colsum[b * 256 + threadIdx.x], s);
}

// ---------------- E = exp(phi_k/(colsum+eps) * V) (no max-shift), accumulate l ----------------
__global__ void e_kernel(const float* __restrict__ V) {
    int b = blockIdx.y, chunk = blockIdx.x;
    int wid = threadIdx.x >> 5, lane = threadIdx.x & 31;
    int e0 = lane * 8;
    float inv[8];
    {
        float4 c0 = *(const float4*)&g_colsum[b * 256 + e0];
        float4 c1 = *(const float4*)&g_colsum[b * 256 + e0 + 4];
        inv[0] = __fdividef(1.f, c0.x + FEPS); inv[1] = __fdividef(1.f, c0.y + FEPS);
        inv[2] = __fdividef(1.f, c0.z + FEPS); inv[3] = __fdividef(1.f, c0.w + FEPS);
        inv[4] = __fdividef(1.f, c1.x + FEPS); inv[5] = __fdividef(1.f, c1.y + FEPS);
        inv[6] = __fdividef(1.f, c1.z + FEPS); inv[7] = __fdividef(1.f, c1.w + FEPS);
    }
    float ls[8] = {};
    for (int it = 0; it < 16; it++) {
        int n = chunk * 128 + it * 8 + wid;
        long base = ((long)b * SEQ + n) * 256 + e0;
        uint4 h = *(const uint4*)(g_pk_hi + base);
        uint4 l = *(const uint4*)(g_pk_lo + base);
        float4 v0 = *(const float4*)(V + base);
        float4 v1 = *(const float4*)(V + base + 4);
        uint32_t hu[4] = {h.x, h.y, h.z, h.w}, lu[4] = {l.x, l.y, l.z, l.w};
        float vv[8] = {v0.x, v0.y, v0.z, v0.w, v1.x, v1.y, v1.z, v1.w};
        float E[8];
#pragma unroll
        for (int p = 0; p < 4; p++) {
            float2 a = unpack_bf16(hu[p]), bb = unpack_bf16(lu[p]);
            E[2 * p]     = __expf((a.x + bb.x) * inv[2 * p] * vv[2 * p]);
            E[2 * p + 1] = __expf((a.y + bb.y) * inv[2 * p + 1] * vv[2 * p + 1]);
        }
        uint32_t ph[4], pl[4];
#pragma unroll
        for (int p = 0; p < 4; p++) {
            float a = E[2 * p], bb = E[2 * p + 1];
            ls[2 * p] += a; ls[2 * p + 1] += bb;
            ph[p] = pack_bf16(a, bb);
            pl[p] = pack_bf16(a - bf16_round(a), bb - bf16_round(bb));
        }
        *(uint4*)(g_E_hi + base) = make_uint4(ph[0], ph[1], ph[2], ph[3]);
        *(uint4*)(g_E_lo + base) = make_uint4(pl[0], pl[1], pl[2], pl[3]);
    }
#pragma unroll
    for (int j = 0; j < 8; j++) atomicAdd(&g_l[b * 256 + e0 + j], ls[j]);
}

// ---------------- KVs = split(KV / l[e]) ----------------
__global__ void kvscale_kernel() {
    long i = (long)blockIdx.x * 256 + threadIdx.x;   // < BATCH*DIM*DIM
    int b = (int)(i >> 16), e = (int)(i & 255);
    float v = g_KV[i] * __fdividef(1.f, g_l[b * 256 + e]);
    g_KVs_hi[i] = __float2bfloat16(v);
    g_KVs_lo[i] = __float2bfloat16(v - bf16_round(v));
}

// ---------------- launch ----------------
extern "C" void kernel_launch(void* const* d_in, const int* in_sizes, int n_in,
                              void* d_out, int out_size) {
    const float* Q  = (const float*)d_in[0];
    const float* K  = (const float*)d_in[1];
    const float* V  = (const float*)d_in[2];
    const float* Wq = (const float*)d_in[3];
    const float* bq = (const float*)d_in[4];
    const float* Wk = (const float*)d_in[5];
    const float* bk = (const float*)d_in[6];
    float* out = (float*)d_out;

    void* p;
    cudaGetSymbolAddress(&p, g_KV);      float* KV = (float*)p;
    cudaGetSymbolAddress(&p, g_rowfac);  float* rowfac = (float*)p;
    cudaGetSymbolAddress(&p, g_Wq_hi);   __nv_bfloat16* Wq_hi = (__nv_bfloat16*)p;
    cudaGetSymbolAddress(&p, g_Wq_lo);   __nv_bfloat16* Wq_lo = (__nv_bfloat16*)p;
    cudaGetSymbolAddress(&p, g_Wk_hi);   __nv_bfloat16* Wk_hi = (__nv_bfloat16*)p;
    cudaGetSymbolAddress(&p, g_Wk_lo);   __nv_bfloat16* Wk_lo = (__nv_bfloat16*)p;
    cudaGetSymbolAddress(&p, g_pq_hi);   __nv_bfloat16* pq_hi = (__nv_bfloat16*)p;
    cudaGetSymbolAddress(&p, g_pq_lo);   __nv_bfloat16* pq_lo = (__nv_bfloat16*)p;
    cudaGetSymbolAddress(&p, g_pk_hi);   __nv_bfloat16* pk_hi = (__nv_bfloat16*)p;
    cudaGetSymbolAddress(&p, g_pk_lo);   __nv_bfloat16* pk_lo = (__nv_bfloat16*)p;
    cudaGetSymbolAddress(&p, g_E_hi);    __nv_bfloat16* E_hi = (__nv_bfloat16*)p;
    cudaGetSymbolAddress(&p, g_E_lo);    __nv_bfloat16* E_lo = (__nv_bfloat16*)p;
    cudaGetSymbolAddress(&p, g_KVs_hi);  __nv_bfloat16* KVs_hi = (__nv_bfloat16*)p;
    cudaGetSymbolAddress(&p, g_KVs_lo);  __nv_bfloat16* KVs_lo = (__nv_bfloat16*)p;

    zero_kernel<<<4096, 256>>>();
    wsplit_kernel<<<dim3(256, 2, 1), 256>>>(Wq, Wk);

    // phi_q / phi_k = sigmoid(X @ W + b), written as bf16 hi/lo pairs
    wgemm<0, 1, 0><<<dim3(512, 2, 1), 256>>>(
        Q, nullptr, Wq_hi, Wq_lo, bq, nullptr, pq_hi, pq_lo, 8, 1, 0, 0, 0, 0);
    wgemm<0, 1, 0><<<dim3(512, 2, 1), 256>>>(
        K, nullptr, Wk_hi, Wk_lo, bk, nullptr, pk_hi, pk_lo, 8, 1, 0, 0, 0, 0);

    rowfac_kernel<<<BATCH * SEQ / 8, 256>>>();
    colsum_kernel<<<BATCH * 32, 256>>>();
    e_kernel<<<dim3(32, BATCH, 1), 256>>>(V);

    // KV[b] = phi_k^T @ E  (A K-major via col_major frags), K-split 8 + atomics
    wgemm<2, 0, 1><<<dim3(2, 2, BATCH * 8), 256>>>(
        pk_hi, pk_lo, E_hi, E_lo, nullptr, KV, nullptr, nullptr,
        16, 8, 512, (long)SEQ * DIM, (long)SEQ * DIM, (long)DIM * DIM);

    kvscale_kernel<<<BATCH * DIM * DIM / 256, 256>>>();

    // R = rowfac * (phi_q @ KVs)
    wgemm<1, 0, 0><<<dim3(32, 2, BATCH), 256>>>(
        pq_hi, pq_lo, KVs_hi, KVs_lo, rowfac, out, nullptr, nullptr,
        8, 1, 0, (long)SEQ * DIM, (long)DIM * DIM, (long)SEQ * DIM);
}

// round 12
// speedup vs baseline: 2.4619x; 1.2726x over previous
#include <cuda_runtime.h>
#include <cuda_bf16.h>
#include <mma.h>
#include <math.h>
#include <stdint.h>

using namespace nvcuda;

#define BATCH 16
#define SEQ   4096
#define DIM   256
#define FEPS  1e-6f

// ---------------- scratch ----------------
__device__ __align__(256) float g_KV[BATCH * DIM * DIM];
__device__ __align__(256) float g_colsum[BATCH * DIM];
__device__ __align__(256) float g_l[BATCH * DIM];
__device__ __align__(256) float g_rowfac[BATCH * SEQ];
__device__ __align__(256) __nv_bfloat16 g_Wq_hi[DIM * DIM];
__device__ __align__(256) __nv_bfloat16 g_Wq_lo[DIM * DIM];
__device__ __align__(256) __nv_bfloat16 g_Wk_hi[DIM * DIM];
__device__ __align__(256) __nv_bfloat16 g_Wk_lo[DIM * DIM];
__device__ __align__(256) __nv_bfloat16 g_Qs_hi[BATCH * SEQ * DIM];
__device__ __align__(256) __nv_bfloat16 g_Qs_lo[BATCH * SEQ * DIM];
__device__ __align__(256) __nv_bfloat16 g_Ks_hi[BATCH * SEQ * DIM];
__device__ __align__(256) __nv_bfloat16 g_Ks_lo[BATCH * SEQ * DIM];
__device__ __align__(256) __nv_bfloat16 g_pq_hi[BATCH * SEQ * DIM];
__device__ __align__(256) __nv_bfloat16 g_pq_lo[BATCH * SEQ * DIM];
__device__ __align__(256) __nv_bfloat16 g_pk_hi[BATCH * SEQ * DIM];
__device__ __align__(256) __nv_bfloat16 g_pk_lo[BATCH * SEQ * DIM];
__device__ __align__(256) __nv_bfloat16 g_E_hi[BATCH * SEQ * DIM];
__device__ __align__(256) __nv_bfloat16 g_E_lo[BATCH * SEQ * DIM];
__device__ __align__(256) __nv_bfloat16 g_KVs_hi[BATCH * DIM * DIM];
__device__ __align__(256) __nv_bfloat16 g_KVs_lo[BATCH * DIM * DIM];

__device__ __forceinline__ float fast_sigmoid(float x) {
    return __fdividef(1.f, 1.f + __expf(-x));
}
__device__ __forceinline__ float bf16_round(float a) {
    return __bfloat162float(__float2bfloat16(a));
}
__device__ __forceinline__ uint32_t pack_bf16(float a, float b) {
    __nv_bfloat162 h = __floats2bfloat162_rn(a, b);
    return (uint32_t)__bfloat16_as_ushort(h.x) | ((uint32_t)__bfloat16_as_ushort(h.y) << 16);
}
__device__ __forceinline__ float2 unpack_bf16(uint32_t u) {
    __nv_bfloat162 t;
    *reinterpret_cast<uint32_t*>(&t) = u;
    return make_float2(__bfloat162float(t.x), __bfloat162float(t.y));
}
__device__ __forceinline__ uint32_t smem_u32(const void* p) {
    uint32_t a;
    asm("{ .reg .u64 t; cvta.to.shared.u64 t, %1; cvt.u32.u64 %0, t; }" : "=r"(a) : "l"(p));
    return a;
}
__device__ __forceinline__ void cp_async16(uint32_t dst, const void* src) {
    asm volatile("cp.async.cg.shared.global [%0], [%1], 16;" :: "r"(dst), "l"(src));
}
#define CP_COMMIT() asm volatile("cp.async.commit_group;" ::: "memory")
#define CP_WAIT1()  asm volatile("cp.async.wait_group 1;" ::: "memory")
#define CP_WAIT0()  asm volatile("cp.async.wait_group 0;" ::: "memory")

// smem geometry (conflict-free strides)
#define A_STR 40      // non-trans A: 128 rows x 32 k, stride 40 elems (80B -> 8-row bank cycle)
#define T_STR 136     // trans A / B: 32 rows x 128, stride 136 elems (272B -> distinct)
#define SZ_A  10240   // 128*40*2
#define SZ_B  8704    // 32*136*2
#define BUF_B 37888   // Ah|Al|Bh|Bl
#define SMEM_WG 75776 // 2 buffers

// ---------------- zero init ----------------
__global__ void zero_kernel() {
    unsigned i = blockIdx.x * blockDim.x + threadIdx.x;
    if (i < BATCH * DIM * DIM) g_KV[i] = 0.f;
    if (i < BATCH * DIM) { g_colsum[i] = 0.f; g_l[i] = 0.f; }
}

// ---------------- W split ----------------
__global__ void wsplit_kernel(const float* __restrict__ Wq, const float* __restrict__ Wk) {
    const float* W = blockIdx.y ? Wk : Wq;
    __nv_bfloat16* oh = blockIdx.y ? g_Wk_hi : g_Wq_hi;
    __nv_bfloat16* ol = blockIdx.y ? g_Wk_lo : g_Wq_lo;
    int i = blockIdx.x * 256 + threadIdx.x;
    float x = W[i];
    oh[i] = __float2bfloat16(x);
    ol[i] = __float2bfloat16(x - bf16_round(x));
}

// ---------------- Q/K split to bf16 hi/lo ----------------
__global__ void qksplit_kernel(const float* __restrict__ Q, const float* __restrict__ Kk) {
    long i = ((long)blockIdx.x * 256 + threadIdx.x) * 4;
    const float* src = blockIdx.y ? Kk : Q;
    __nv_bfloat16* oh = blockIdx.y ? g_Ks_hi : g_Qs_hi;
    __nv_bfloat16* ol = blockIdx.y ? g_Ks_lo : g_Qs_lo;
    float4 v = *(const float4*)(src + i);
    *(uint2*)(oh + i) = make_uint2(pack_bf16(v.x, v.y), pack_bf16(v.z, v.w));
    *(uint2*)(ol + i) = make_uint2(
        pack_bf16(v.x - bf16_round(v.x), v.y - bf16_round(v.y)),
        pack_bf16(v.z - bf16_round(v.z), v.w - bf16_round(v.w)));
}

// ============ WMMA bf16-split GEMM, cp.async double-buffered ============
// CTA tile 128x128, 8 warps (4m x 2n), K-chunk 32.
// MODE 0: Chi/Clo = split(sigmoid(acc + bias[col]))
// MODE 1: C = rowfac[z*SEQ+row] * acc
// MODE 2: atomicAdd(C, acc)
// ATRANS: A is K-major: element (m,k) at A[k*256 + m]
template <int MODE, int ATRANS>
__device__ __forceinline__ void issue_chunk(uint32_t sa,
    const __nv_bfloat16* Ah, const __nv_bfloat16* Al,
    const __nv_bfloat16* Bh, const __nv_bfloat16* Bl,
    long aBase, long bBase, int k0)
{
    int tid = threadIdx.x;
#pragma unroll
    for (int i = 0; i < 2; i++) {
        int idx = tid + i * 256;
        if (!ATRANS) {
            int r = idx >> 2, cc = idx & 3;
            long src = aBase + (long)r * 256 + k0 + cc * 8;
            uint32_t dst = sa + (r * A_STR + cc * 8) * 2;
            cp_async16(dst, Ah + src);
            cp_async16(dst + SZ_A, Al + src);
        } else {
            int r = idx >> 4, cc = idx & 15;
            long src = aBase + (long)(k0 + r) * 256 + cc * 8;
            uint32_t dst = sa + (r * T_STR + cc * 8) * 2;
            cp_async16(dst, Ah + src);
            cp_async16(dst + SZ_A, Al + src);
        }
        {
            int r = idx >> 4, cc = idx & 15;
            long src = bBase + (long)(k0 + r) * 256 + cc * 8;
            uint32_t dst = sa + 2 * SZ_A + (r * T_STR + cc * 8) * 2;
            cp_async16(dst, Bh + src);
            cp_async16(dst + SZ_B, Bl + src);
        }
    }
}

template <int MODE, int ATRANS>
__global__ __launch_bounds__(256, 2) void wgemm(
    const __nv_bfloat16* __restrict__ Ahp, const __nv_bfloat16* __restrict__ Alp,
    const __nv_bfloat16* __restrict__ Bhp, const __nv_bfloat16* __restrict__ Blp,
    const float* __restrict__ aux, float* C,
    __nv_bfloat16* Chi, __nv_bfloat16* Clo,
    int kchunks, int ksplit, int ksplitlen,
    long Az, long Bz, long Cz)
{
    extern __shared__ __align__(128) char smem[];
    int tid = threadIdx.x;
    int wid = tid >> 5;
    int warp_m = wid & 3, warp_n = wid >> 2;
    int bm = blockIdx.x, bn = blockIdx.y;
    int z = blockIdx.z / ksplit;
    int k0base = (blockIdx.z % ksplit) * ksplitlen;

    long aBase = ATRANS ? (z * Az + (long)bm * 128)
                        : (z * Az + (long)bm * 128 * 256);
    long bBase = z * Bz + (long)bn * 128;
    uint32_t sbase = smem_u32(smem);

    wmma::fragment<wmma::accumulator, 16, 16, 16, float> acc[2][4];
#pragma unroll
    for (int i = 0; i < 2; i++)
#pragma unroll
        for (int j = 0; j < 4; j++) wmma::fill_fragment(acc[i][j], 0.f);

    issue_chunk<MODE, ATRANS>(sbase, Ahp, Alp, Bhp, Blp, aBase, bBase, k0base);
    CP_COMMIT();

    for (int c = 0; c < kchunks; c++) {
        if (c + 1 < kchunks) {
            issue_chunk<MODE, ATRANS>(sbase + ((c + 1) & 1) * BUF_B,
                Ahp, Alp, Bhp, Blp, aBase, bBase, k0base + (c + 1) * 32);
            CP_COMMIT();
            CP_WAIT1();
        } else {
            CP_WAIT0();
        }
        __syncthreads();

        char* buf = smem + (c & 1) * BUF_B;
        __nv_bfloat16* sAh = (__nv_bfloat16*)buf;
        __nv_bfloat16* sAl = sAh + SZ_A / 2;
        __nv_bfloat16* sBh = (__nv_bfloat16*)(buf + 2 * SZ_A);
        __nv_bfloat16* sBl = sBh + SZ_B / 2;

#pragma unroll
        for (int kk = 0; kk < 32; kk += 16) {
            wmma::fragment<wmma::matrix_b, 16, 16, 16, __nv_bfloat16, wmma::row_major> bh[4], bl[4];
#pragma unroll
            for (int j = 0; j < 4; j++) {
                int n0 = warp_n * 64 + j * 16;
                wmma::load_matrix_sync(bh[j], &sBh[kk * T_STR + n0], T_STR);
                wmma::load_matrix_sync(bl[j], &sBl[kk * T_STR + n0], T_STR);
            }
            if (ATRANS) {
                wmma::fragment<wmma::matrix_a, 16, 16, 16, __nv_bfloat16, wmma::col_major> ah[2], al[2];
#pragma unroll
                for (int i = 0; i < 2; i++) {
                    int m0 = warp_m * 32 + i * 16;
                    wmma::load_matrix_sync(ah[i], &sAh[kk * T_STR + m0], T_STR);
                    wmma::load_matrix_sync(al[i], &sAl[kk * T_STR + m0], T_STR);
                }
#pragma unroll
                for (int i = 0; i < 2; i++)
#pragma unroll
                    for (int j = 0; j < 4; j++) {
                        wmma::mma_sync(acc[i][j], ah[i], bh[j], acc[i][j]);
                        wmma::mma_sync(acc[i][j], al[i], bh[j], acc[i][j]);
                        wmma::mma_sync(acc[i][j], ah[i], bl[j], acc[i][j]);
                    }
            } else {
                wmma::fragment<wmma::matrix_a, 16, 16, 16, __nv_bfloat16, wmma::row_major> ah[2], al[2];
#pragma unroll
                for (int i = 0; i < 2; i++) {
                    int m0 = warp_m * 32 + i * 16;
                    wmma::load_matrix_sync(ah[i], &sAh[m0 * A_STR + kk], A_STR);
                    wmma::load_matrix_sync(al[i], &sAl[m0 * A_STR + kk], A_STR);
                }
#pragma unroll
                for (int i = 0; i < 2; i++)
#pragma unroll
                    for (int j = 0; j < 4; j++) {
                        wmma::mma_sync(acc[i][j], ah[i], bh[j], acc[i][j]);
                        wmma::mma_sync(acc[i][j], al[i], bh[j], acc[i][j]);
                        wmma::mma_sync(acc[i][j], ah[i], bl[j], acc[i][j]);
                    }
            }
        }
        __syncthreads();
    }

    // ---- epilogue via fp32 staging, two 64-col halves ----
    float* stage = (float*)smem;
#pragma unroll
    for (int h = 0; h < 2; h++) {
        if (warp_n == h) {
#pragma unroll
            for (int i = 0; i < 2; i++)
#pragma unroll
                for (int j = 0; j < 4; j++)
                    wmma::store_matrix_sync(&stage[(warp_m * 32 + i * 16) * 72 + j * 16],
                                            acc[i][j], 72, wmma::mem_row_major);
        }
        __syncthreads();
        int r = tid >> 1, c0 = (tid & 1) * 32;
        int colg = bn * 128 + h * 64 + c0;
        long row_g = (long)bm * 128 + r;
        float v[32];
#pragma unroll
        for (int j = 0; j < 32; j++) v[j] = stage[r * 72 + c0 + j];
        if (MODE == 0) {
            long off = row_g * 256 + colg;
            uint32_t ph[16], pl[16];
#pragma unroll
            for (int p = 0; p < 16; p++) {
                float a = fast_sigmoid(v[2 * p] + aux[colg + 2 * p]);
                float b = fast_sigmoid(v[2 * p + 1] + aux[colg + 2 * p + 1]);
                ph[p] = pack_bf16(a, b);
                pl[p] = pack_bf16(a - bf16_round(a), b - bf16_round(b));
            }
#pragma unroll
            for (int p = 0; p < 16; p += 4) {
                *(uint4*)(Chi + off + 2 * p) = make_uint4(ph[p], ph[p + 1], ph[p + 2], ph[p + 3]);
                *(uint4*)(Clo + off + 2 * p) = make_uint4(pl[p], pl[p + 1], pl[p + 2], pl[p + 3]);
            }
        } else if (MODE == 1) {
            float f = aux[(long)z * SEQ + row_g];
            long off = z * Cz + row_g * 256 + colg;
#pragma unroll
            for (int j = 0; j < 32; j += 4)
                *(float4*)(C + off + j) = make_float4(f * v[j], f * v[j + 1], f * v[j + 2], f * v[j + 3]);
        } else {
            long off = z * Cz + row_g * 256 + colg;
#pragma unroll
            for (int j = 0; j < 32; j++) atomicAdd(C + off + j, v[j]);
        }
        __syncthreads();
    }
}

// ---------------- rowfac ----------------
__global__ void rowfac_kernel() {
    int warp = threadIdx.x >> 5, lane = threadIdx.x & 31;
    long row = (long)blockIdx.x * 8 + warp;
    long base = row * 256 + lane * 8;
    uint4 h = *(const uint4*)(g_pq_hi + base);
    uint4 l = *(const uint4*)(g_pq_lo + base);
    float s = 0.f;
    uint32_t hu[4] = {h.x, h.y, h.z, h.w}, lu[4] = {l.x, l.y, l.z, l.w};
#pragma unroll
    for (int p = 0; p < 4; p++) {
        float2 a = unpack_bf16(hu[p]), b = unpack_bf16(lu[p]);
        s += a.x + a.y + b.x + b.y;
    }
#pragma unroll
    for (int off = 16; off; off >>= 1) s += __shfl_xor_sync(0xffffffffu, s, off);
    if (lane == 0) g_rowfac[row] = fast_sigmoid(s) * __fdividef(1.f, s + FEPS);
}

// ---------------- colsum ----------------
__global__ void colsum_kernel() {
    int b = blockIdx.x >> 5, ns = blockIdx.x & 31;
    long base = ((long)b * SEQ + (long)ns * 128) * 256 + threadIdx.x;
    float s = 0.f;
#pragma unroll 4
    for (int n = 0; n < 128; n++) {
        long o = base + (long)n * 256;
        s += __bfloat162float(g_pk_hi[o]) + __bfloat162float(g_pk_lo[o]);
    }
    atomicAdd(&g_colsum[b * 256 + threadIdx.x], s);
}

// ---------------- E = exp(phi_k/(colsum+eps) * V), accumulate l ----------------
__global__ void e_kernel(const float* __restrict__ V) {
    int b = blockIdx.y, chunk = blockIdx.x;
    int wid = threadIdx.x >> 5, lane = threadIdx.x & 31;
    int e0 = lane * 8;
    float inv[8];
    {
        float4 c0 = *(const float4*)&g_colsum[b * 256 + e0];
        float4 c1 = *(const float4*)&g_colsum[b * 256 + e0 + 4];
        inv[0] = __fdividef(1.f, c0.x + FEPS); inv[1] = __fdividef(1.f, c0.y + FEPS);
        inv[2] = __fdividef(1.f, c0.z + FEPS); inv[3] = __fdividef(1.f, c0.w + FEPS);
        inv[4] = __fdividef(1.f, c1.x + FEPS); inv[5] = __fdividef(1.f, c1.y + FEPS);
        inv[6] = __fdividef(1.f, c1.z + FEPS); inv[7] = __fdividef(1.f, c1.w + FEPS);
    }
    float ls[8] = {};
    for (int it = 0; it < 16; it++) {
        int n = chunk * 128 + it * 8 + wid;
        long base = ((long)b * SEQ + n) * 256 + e0;
        uint4 h = *(const uint4*)(g_pk_hi + base);
        uint4 l = *(const uint4*)(g_pk_lo + base);
        float4 v0 = *(const float4*)(V + base);
        float4 v1 = *(const float4*)(V + base + 4);
        uint32_t hu[4] = {h.x, h.y, h.z, h.w}, lu[4] = {l.x, l.y, l.z, l.w};
        float vv[8] = {v0.x, v0.y, v0.z, v0.w, v1.x, v1.y, v1.z, v1.w};
        float E[8];
#pragma unroll
        for (int p = 0; p < 4; p++) {
            float2 a = unpack_bf16(hu[p]), bb = unpack_bf16(lu[p]);
            E[2 * p]     = __expf((a.x + bb.x) * inv[2 * p] * vv[2 * p]);
            E[2 * p + 1] = __expf((a.y + bb.y) * inv[2 * p + 1] * vv[2 * p + 1]);
        }
        uint32_t ph[4], pl[4];
#pragma unroll
        for (int p = 0; p < 4; p++) {
            float a = E[2 * p], bb = E[2 * p + 1];
            ls[2 * p] += a; ls[2 * p + 1] += bb;
            ph[p] = pack_bf16(a, bb);
            pl[p] = pack_bf16(a - bf16_round(a), bb - bf16_round(bb));
        }
        *(uint4*)(g_E_hi + base) = make_uint4(ph[0], ph[1], ph[2], ph[3]);
        *(uint4*)(g_E_lo + base) = make_uint4(pl[0], pl[1], pl[2], pl[3]);
    }
#pragma unroll
    for (int j = 0; j < 8; j++) atomicAdd(&g_l[b * 256 + e0 + j], ls[j]);
}

// ---------------- KVs = split(KV / l[e]) ----------------
__global__ void kvscale_kernel() {
    long i = (long)blockIdx.x * 256 + threadIdx.x;
    int b = (int)(i >> 16), e = (int)(i & 255);
    float v = g_KV[i] * __fdividef(1.f, g_l[b * 256 + e]);
    g_KVs_hi[i] = __float2bfloat16(v);
    g_KVs_lo[i] = __float2bfloat16(v - bf16_round(v));
}

// ---------------- launch ----------------
extern "C" void kernel_launch(void* const* d_in, const int* in_sizes, int n_in,
                              void* d_out, int out_size) {
    const float* Q  = (const float*)d_in[0];
    const float* K  = (const float*)d_in[1];
    const float* V  = (const float*)d_in[2];
    const float* Wq = (const float*)d_in[3];
    const float* bq = (const float*)d_in[4];
    const float* Wk = (const float*)d_in[5];
    const float* bk = (const float*)d_in[6];
    float* out = (float*)d_out;

    cudaFuncSetAttribute(wgemm<0, 0>, cudaFuncAttributeMaxDynamicSharedMemorySize, SMEM_WG);
    cudaFuncSetAttribute(wgemm<2, 1>, cudaFuncAttributeMaxDynamicSharedMemorySize, SMEM_WG);
    cudaFuncSetAttribute(wgemm<1, 0>, cudaFuncAttributeMaxDynamicSharedMemorySize, SMEM_WG);

    void* p;
    cudaGetSymbolAddress(&p, g_KV);      float* KV = (float*)p;
    cudaGetSymbolAddress(&p, g_rowfac);  float* rowfac = (float*)p;
    cudaGetSymbolAddress(&p, g_Wq_hi);   __nv_bfloat16* Wq_hi = (__nv_bfloat16*)p;
    cudaGetSymbolAddress(&p, g_Wq_lo);   __nv_bfloat16* Wq_lo = (__nv_bfloat16*)p;
    cudaGetSymbolAddress(&p, g_Wk_hi);   __nv_bfloat16* Wk_hi = (__nv_bfloat16*)p;
    cudaGetSymbolAddress(&p, g_Wk_lo);   __nv_bfloat16* Wk_lo = (__nv_bfloat16*)p;
    cudaGetSymbolAddress(&p, g_Qs_hi);   __nv_bfloat16* Qs_hi = (__nv_bfloat16*)p;
    cudaGetSymbolAddress(&p, g_Qs_lo);   __nv_bfloat16* Qs_lo = (__nv_bfloat16*)p;
    cudaGetSymbolAddress(&p, g_Ks_hi);   __nv_bfloat16* Ks_hi = (__nv_bfloat16*)p;
    cudaGetSymbolAddress(&p, g_Ks_lo);   __nv_bfloat16* Ks_lo = (__nv_bfloat16*)p;
    cudaGetSymbolAddress(&p, g_pq_hi);   __nv_bfloat16* pq_hi = (__nv_bfloat16*)p;
    cudaGetSymbolAddress(&p, g_pq_lo);   __nv_bfloat16* pq_lo = (__nv_bfloat16*)p;
    cudaGetSymbolAddress(&p, g_pk_hi);   __nv_bfloat16* pk_hi = (__nv_bfloat16*)p;
    cudaGetSymbolAddress(&p, g_pk_lo);   __nv_bfloat16* pk_lo = (__nv_bfloat16*)p;
    cudaGetSymbolAddress(&p, g_E_hi);    __nv_bfloat16* E_hi = (__nv_bfloat16*)p;
    cudaGetSymbolAddress(&p, g_E_lo);    __nv_bfloat16* E_lo = (__nv_bfloat16*)p;
    cudaGetSymbolAddress(&p, g_KVs_hi);  __nv_bfloat16* KVs_hi = (__nv_bfloat16*)p;
    cudaGetSymbolAddress(&p, g_KVs_lo);  __nv_bfloat16* KVs_lo = (__nv_bfloat16*)p;

    zero_kernel<<<4096, 256>>>();
    wsplit_kernel<<<dim3(256, 2, 1), 256>>>(Wq, Wk);
    qksplit_kernel<<<dim3(BATCH * SEQ * DIM / 1024, 2, 1), 256>>>(Q, K);

    // phi_q / phi_k = sigmoid(X @ W + b), bf16 hi/lo out
    wgemm<0, 0><<<dim3(512, 2, 1), 256, SMEM_WG>>>(
        Qs_hi, Qs_lo, Wq_hi, Wq_lo, bq, nullptr, pq_hi, pq_lo, 8, 1, 0, 0, 0, 0);
    wgemm<0, 0><<<dim3(512, 2, 1), 256, SMEM_WG>>>(
        Ks_hi, Ks_lo, Wk_hi, Wk_lo, bk, nullptr, pk_hi, pk_lo, 8, 1, 0, 0, 0, 0);

    rowfac_kernel<<<BATCH * SEQ / 8, 256>>>();
    colsum_kernel<<<BATCH * 32, 256>>>();
    e_kernel<<<dim3(32, BATCH, 1), 256>>>(V);

    // KV[b] = phi_k^T @ E, K-split 8 + atomics
    wgemm<2, 1><<<dim3(2, 2, BATCH * 8), 256, SMEM_WG>>>(
        pk_hi, pk_lo, E_hi, E_lo, nullptr, KV, nullptr, nullptr,
        16, 8, 512, (long)SEQ * DIM, (long)SEQ * DIM, (long)DIM * DIM);

    kvscale_kernel<<<BATCH * DIM * DIM / 256, 256>>>();

    // R = rowfac * (phi_q @ KVs)
    wgemm<1, 0><<<dim3(32, 2, BATCH), 256, SMEM_WG>>>(
        pq_hi, pq_lo, KVs_hi, KVs_lo, rowfac, out, nullptr, nullptr,
        8, 1, 0, (long)SEQ * DIM, (long)DIM * DIM, (long)SEQ * DIM);
}

// round 16
// speedup vs baseline: 2.6056x; 1.0584x over previous
#include <cuda_runtime.h>
#include <cuda_bf16.h>
#include <math.h>
#include <stdint.h>

#define BATCH 16
#define SEQ   4096
#define DIM   256
#define FEPS  1e-6f

// ---------------- scratch ----------------
__device__ __align__(256) float g_KV[BATCH * DIM * DIM];
__device__ __align__(256) float g_colsum[BATCH * DIM];
__device__ __align__(256) float g_l[BATCH * DIM];
__device__ __align__(256) float g_rowfac[BATCH * SEQ];
__device__ __align__(256) __nv_bfloat16 g_Wq_hi[DIM * DIM];
__device__ __align__(256) __nv_bfloat16 g_Wq_lo[DIM * DIM];
__device__ __align__(256) __nv_bfloat16 g_Wk_hi[DIM * DIM];
__device__ __align__(256) __nv_bfloat16 g_Wk_lo[DIM * DIM];
__device__ __align__(256) __nv_bfloat16 g_Qs_hi[BATCH * SEQ * DIM];
__device__ __align__(256) __nv_bfloat16 g_Qs_lo[BATCH * SEQ * DIM];
__device__ __align__(256) __nv_bfloat16 g_Ks_hi[BATCH * SEQ * DIM];
__device__ __align__(256) __nv_bfloat16 g_Ks_lo[BATCH * SEQ * DIM];
__device__ __align__(256) __nv_bfloat16 g_pq_hi[BATCH * SEQ * DIM];
__device__ __align__(256) __nv_bfloat16 g_pq_lo[BATCH * SEQ * DIM];
__device__ __align__(256) __nv_bfloat16 g_pk_hi[BATCH * SEQ * DIM];
__device__ __align__(256) __nv_bfloat16 g_pk_lo[BATCH * SEQ * DIM];
__device__ __align__(256) __nv_bfloat16 g_E_hi[BATCH * SEQ * DIM];
__device__ __align__(256) __nv_bfloat16 g_E_lo[BATCH * SEQ * DIM];
__device__ __align__(256) __nv_bfloat16 g_KVs_hi[BATCH * DIM * DIM];
__device__ __align__(256) __nv_bfloat16 g_KVs_lo[BATCH * DIM * DIM];

__device__ __forceinline__ float fast_sigmoid(float x) {
    return __fdividef(1.f, 1.f + __expf(-x));
}
__device__ __forceinline__ float bf16_round(float a) {
    return __bfloat162float(__float2bfloat16(a));
}
__device__ __forceinline__ uint32_t pack_bf16(float a, float b) {
    __nv_bfloat162 h = __floats2bfloat162_rn(a, b);
    return (uint32_t)__bfloat16_as_ushort(h.x) | ((uint32_t)__bfloat16_as_ushort(h.y) << 16);
}
__device__ __forceinline__ float2 unpack_bf16(uint32_t u) {
    __nv_bfloat162 t;
    *reinterpret_cast<uint32_t*>(&t) = u;
    return make_float2(__bfloat162float(t.x), __bfloat162float(t.y));
}
__device__ __forceinline__ uint32_t smem_u32(const void* p) {
    uint32_t a;
    asm("{ .reg .u64 t; cvta.to.shared.u64 t, %1; cvt.u32.u64 %0, t; }" : "=r"(a) : "l"(p));
    return a;
}
__device__ __forceinline__ void cp_async16(uint32_t dst, const void* src) {
    asm volatile("cp.async.cg.shared.global [%0], [%1], 16;" :: "r"(dst), "l"(src));
}
#define CP_COMMIT() asm volatile("cp.async.commit_group;" ::: "memory")
#define CP_WAIT2()  asm volatile("cp.async.wait_group 2;" ::: "memory")
#define CP_WAIT1()  asm volatile("cp.async.wait_group 1;" ::: "memory")
#define CP_WAIT0()  asm volatile("cp.async.wait_group 0;" ::: "memory")

__device__ __forceinline__ void ldsm4(uint32_t* r, uint32_t a) {
    asm volatile("ldmatrix.sync.aligned.m8n8.x4.shared.b16 {%0,%1,%2,%3}, [%4];"
        : "=r"(r[0]), "=r"(r[1]), "=r"(r[2]), "=r"(r[3]) : "r"(a));
}
__device__ __forceinline__ void ldsm4t(uint32_t* r, uint32_t a) {
    asm volatile("ldmatrix.sync.aligned.m8n8.x4.trans.shared.b16 {%0,%1,%2,%3}, [%4];"
        : "=r"(r[0]), "=r"(r[1]), "=r"(r[2]), "=r"(r[3]) : "r"(a));
}
__device__ __forceinline__ void mma16816(float* d, const uint32_t* a, const uint32_t* b) {
    asm volatile("mma.sync.aligned.m16n8k16.row.col.f32.bf16.bf16.f32 "
        "{%0,%1,%2,%3}, {%4,%5,%6,%7}, {%8,%9}, {%0,%1,%2,%3};"
        : "+f"(d[0]), "+f"(d[1]), "+f"(d[2]), "+f"(d[3])
        : "r"(a[0]), "r"(a[1]), "r"(a[2]), "r"(a[3]), "r"(b[0]), "r"(b[1]));
}

// smem stage geometry (bytes). All row strides conflict-free mod 128.
#define ASTR_B   80     // A non-trans: 128 rows x 32k
#define ATSTR_B  272    // A trans: 32 rows x 128m
#define BSTR_B   592    // B: 32 rows x 256n
#define OFF_AL   10240
#define OFF_BH   20480
#define OFF_BL   39424  // 20480 + 18944
#define STAGE_B  58368
#define SMEM_MG  175104 // 3 stages

// ---------------- zero init ----------------
__global__ void zero_kernel() {
    unsigned i = blockIdx.x * blockDim.x + threadIdx.x;
    if (i < BATCH * DIM * DIM) g_KV[i] = 0.f;
    if (i < BATCH * DIM) { g_colsum[i] = 0.f; g_l[i] = 0.f; }
}

// ---------------- W split ----------------
__global__ void wsplit_kernel(const float* __restrict__ Wq, const float* __restrict__ Wk) {
    const float* W = blockIdx.y ? Wk : Wq;
    __nv_bfloat16* oh = blockIdx.y ? g_Wk_hi : g_Wq_hi;
    __nv_bfloat16* ol = blockIdx.y ? g_Wk_lo : g_Wq_lo;
    int i = blockIdx.x * 256 + threadIdx.x;
    float x = W[i];
    oh[i] = __float2bfloat16(x);
    ol[i] = __float2bfloat16(x - bf16_round(x));
}

// ---------------- Q/K split ----------------
__global__ void qksplit_kernel(const float* __restrict__ Q, const float* __restrict__ Kk) {
    long i = ((long)blockIdx.x * 256 + threadIdx.x) * 4;
    const float* src = blockIdx.y ? Kk : Q;
    __nv_bfloat16* oh = blockIdx.y ? g_Ks_hi : g_Qs_hi;
    __nv_bfloat16* ol = blockIdx.y ? g_Ks_lo : g_Qs_lo;
    float4 v = *(const float4*)(src + i);
    *(uint2*)(oh + i) = make_uint2(pack_bf16(v.x, v.y), pack_bf16(v.z, v.w));
    *(uint2*)(ol + i) = make_uint2(
        pack_bf16(v.x - bf16_round(v.x), v.y - bf16_round(v.y)),
        pack_bf16(v.z - bf16_round(v.z), v.w - bf16_round(v.w)));
}

// ============ raw mma.sync bf16-split GEMM ============
// CTA tile 128 x 256 (full N), 8 warps = 2(m) x 4(n), warp tile 64x64, K-chunk 32.
// MODE 0: Chi/Clo = split(sigmoid(acc + bias[col]))
// MODE 1: C = rowfac[z*SEQ+row] * acc
// MODE 2: atomicAdd(C, acc)
// ATRANS: A element (m,k) at A[k*256 + m]
template <int ATRANS>
__device__ __forceinline__ void mg_issue(uint32_t sa,
    const __nv_bfloat16* Ah, const __nv_bfloat16* Al,
    const __nv_bfloat16* Bh, const __nv_bfloat16* Bl,
    long aBase, long bBase, int k0)
{
    int tid = threadIdx.x;
#pragma unroll
    for (int i = 0; i < 2; i++) {
        int idx = tid + i * 256;
        if (!ATRANS) {
            int r = idx >> 2, c = idx & 3;
            long src = aBase + (long)r * 256 + k0 + c * 8;
            uint32_t dst = sa + r * ASTR_B + c * 16;
            cp_async16(dst, Ah + src);
            cp_async16(dst + OFF_AL, Al + src);
        } else {
            int r = idx >> 4, c = idx & 15;
            long src = aBase + (long)(k0 + r) * 256 + c * 8;
            uint32_t dst = sa + r * ATSTR_B + c * 16;
            cp_async16(dst, Ah + src);
            cp_async16(dst + OFF_AL, Al + src);
        }
    }
#pragma unroll
    for (int i = 0; i < 4; i++) {
        int idx = tid + i * 256;
        int r = idx >> 5, c = idx & 31;
        long src = bBase + (long)(k0 + r) * 256 + c * 8;
        uint32_t dst = sa + OFF_BH + r * BSTR_B + c * 16;
        cp_async16(dst, Bh + src);
        cp_async16(dst + (OFF_BL - OFF_BH), Bl + src);
    }
}

template <int MODE, int ATRANS>
__global__ __launch_bounds__(256, 1) void mgemm(
    const __nv_bfloat16* __restrict__ Ahp, const __nv_bfloat16* __restrict__ Alp,
    const __nv_bfloat16* __restrict__ Bhp, const __nv_bfloat16* __restrict__ Blp,
    const float* __restrict__ aux, float* C,
    __nv_bfloat16* Chi, __nv_bfloat16* Clo,
    int kchunks, int ksplit, int ksplitlen,
    long Az, long Bz, long Cz)
{
    extern __shared__ __align__(128) char smem[];
    int tid = threadIdx.x;
    int wid = tid >> 5, lane = tid & 31;
    int warp_m = wid & 1, warp_n = wid >> 1;
    int bm = blockIdx.x;
    int z = blockIdx.z / ksplit;
    int k0base = (blockIdx.z % ksplit) * ksplitlen;

    long aBase = ATRANS ? (z * Az + (long)bm * 128)
                        : (z * Az + (long)bm * 128 * 256);
    long bBase = z * Bz;
    uint32_t sb = smem_u32(smem);

    // lane-derived ldmatrix address offsets (bytes)
    uint32_t aoff;
    if (!ATRANS) {
        // row = m0 + lane%16, col = kk + (lane/16)*8
        aoff = (uint32_t)((lane & 15) * ASTR_B + (lane >> 4) * 16);
    } else {
        // row = kk + (lane&7) + ((lane&16)>>1), col = m0 + (lane&8)
        aoff = (uint32_t)((((lane & 7) | ((lane & 16) >> 1)) * ATSTR_B) + (lane & 8) * 2);
    }
    uint32_t boff = (uint32_t)((lane & 15) * BSTR_B + (lane >> 4) * 16);

    float acc[4][8][4];
#pragma unroll
    for (int i = 0; i < 4; i++)
#pragma unroll
        for (int j = 0; j < 8; j++)
#pragma unroll
            for (int q = 0; q < 4; q++) acc[i][j][q] = 0.f;

    mg_issue<ATRANS>(sb, Ahp, Alp, Bhp, Blp, aBase, bBase, k0base);
    CP_COMMIT();
    mg_issue<ATRANS>(sb + STAGE_B, Ahp, Alp, Bhp, Blp, aBase, bBase, k0base + 32);
    CP_COMMIT();

    int m0w = warp_m * 64, n0w = warp_n * 64;
    for (int c = 0; c < kchunks; c++) {
        if (c + 2 < kchunks) {
            mg_issue<ATRANS>(sb + ((c + 2) % 3) * STAGE_B,
                Ahp, Alp, Bhp, Blp, aBase, bBase, k0base + (c + 2) * 32);
            CP_COMMIT();
            CP_WAIT2();
        } else if (c + 1 < kchunks) {
            CP_WAIT1();
        } else {
            CP_WAIT0();
        }
        __syncthreads();

        uint32_t sa = sb + (c % 3) * STAGE_B;
#pragma unroll
        for (int kk = 0; kk < 32; kk += 16) {
            uint32_t ah[4][4], al[4][4];
#pragma unroll
            for (int i = 0; i < 4; i++) {
                uint32_t abase;
                if (!ATRANS)
                    abase = sa + (m0w + i * 16) * ASTR_B + kk * 2 + aoff;
                else
                    abase = sa + kk * ATSTR_B + (m0w + i * 16) * 2 + aoff;
                ldsm4(ah[i], abase);
                ldsm4(al[i], abase + OFF_AL);
            }
#pragma unroll
            for (int j = 0; j < 4; j++) {
                uint32_t bh[4], bl[4];
                uint32_t bbase = sa + OFF_BH + kk * BSTR_B + (n0w + j * 16) * 2 + boff;
                ldsm4t(bh, bbase);
                ldsm4t(bl, bbase + (OFF_BL - OFF_BH));
#pragma unroll
                for (int i = 0; i < 4; i++) {
                    mma16816(acc[i][2 * j],     ah[i], bh);
                    mma16816(acc[i][2 * j],     al[i], bh);
                    mma16816(acc[i][2 * j],     ah[i], bl);
                    mma16816(acc[i][2 * j + 1], ah[i], bh + 2);
                    mma16816(acc[i][2 * j + 1], al[i], bh + 2);
                    mma16816(acc[i][2 * j + 1], ah[i], bl + 2);
                }
            }
        }
        __syncthreads();
    }

    // ---- epilogue via fp32 staging, four 64-col quarters ----
    float* stage = (float*)smem;
#pragma unroll
    for (int q = 0; q < 4; q++) {
        if (warp_n == q) {
#pragma unroll
            for (int i = 0; i < 4; i++)
#pragma unroll
                for (int j = 0; j < 8; j++) {
                    int r0 = warp_m * 64 + i * 16 + (lane >> 2);
                    int c0 = j * 8 + (lane & 3) * 2;
                    stage[r0 * 72 + c0]           = acc[i][j][0];
                    stage[r0 * 72 + c0 + 1]       = acc[i][j][1];
                    stage[(r0 + 8) * 72 + c0]     = acc[i][j][2];
                    stage[(r0 + 8) * 72 + c0 + 1] = acc[i][j][3];
                }
        }
        __syncthreads();
        int r = tid >> 1, ch = (tid & 1) * 32;
        int colg = q * 64 + ch;
        long row_g = (long)bm * 128 + r;
        float v[32];
#pragma unroll
        for (int j = 0; j < 32; j++) v[j] = stage[r * 72 + ch + j];
        if (MODE == 0) {
            long off = row_g * 256 + colg;
            uint32_t ph[16], pl[16];
#pragma unroll
            for (int p = 0; p < 16; p++) {
                float a = fast_sigmoid(v[2 * p] + aux[colg + 2 * p]);
                float b = fast_sigmoid(v[2 * p + 1] + aux[colg + 2 * p + 1]);
                ph[p] = pack_bf16(a, b);
                pl[p] = pack_bf16(a - bf16_round(a), b - bf16_round(b));
            }
#pragma unroll
            for (int p = 0; p < 16; p += 4) {
                *(uint4*)(Chi + off + 2 * p) = make_uint4(ph[p], ph[p + 1], ph[p + 2], ph[p + 3]);
                *(uint4*)(Clo + off + 2 * p) = make_uint4(pl[p], pl[p + 1], pl[p + 2], pl[p + 3]);
            }
        } else if (MODE == 1) {
            float f = aux[(long)z * SEQ + row_g];
            long off = z * Cz + row_g * 256 + colg;
#pragma unroll
            for (int j = 0; j < 32; j += 4)
                *(float4*)(C + off + j) = make_float4(f * v[j], f * v[j + 1], f * v[j + 2], f * v[j + 3]);
        } else {
            long off = z * Cz + row_g * 256 + colg;
#pragma unroll
            for (int j = 0; j < 32; j++) atomicAdd(C + off + j, v[j]);
        }
        __syncthreads();
    }
}

// ---------------- rowfac ----------------
__global__ void rowfac_kernel() {
    int warp = threadIdx.x >> 5, lane = threadIdx.x & 31;
    long row = (long)blockIdx.x * 8 + warp;
    long base = row * 256 + lane * 8;
    uint4 h = *(const uint4*)(g_pq_hi + base);
    uint4 l = *(const uint4*)(g_pq_lo + base);
    float s = 0.f;
    uint32_t hu[4] = {h.x, h.y, h.z, h.w}, lu[4] = {l.x, l.y, l.z, l.w};
#pragma unroll
    for (int p = 0; p < 4; p++) {
        float2 a = unpack_bf16(hu[p]), b = unpack_bf16(lu[p]);
        s += a.x + a.y + b.x + b.y;
    }
#pragma unroll
    for (int off = 16; off; off >>= 1) s += __shfl_xor_sync(0xffffffffu, s, off);
    if (lane == 0) g_rowfac[row] = fast_sigmoid(s) * __fdividef(1.f, s + FEPS);
}

// ---------------- colsum ----------------
__global__ void colsum_kernel() {
    int b = blockIdx.x >> 5, ns = blockIdx.x & 31;
    long base = ((long)b * SEQ + (long)ns * 128) * 256 + threadIdx.x;
    float s = 0.f;
#pragma unroll 4
    for (int n = 0; n < 128; n++) {
        long o = base + (long)n * 256;
        s += __bfloat162float(g_pk_hi[o]) + __bfloat162float(g_pk_lo[o]);
    }
    atomicAdd(&g_colsum[b * 256 + threadIdx.x], s);
}

// ---------------- E = exp(phi_k/(colsum+eps) * V), accumulate l ----------------
__global__ void e_kernel(const float* __restrict__ V) {
    int b = blockIdx.y, chunk = blockIdx.x;
    int wid = threadIdx.x >> 5, lane = threadIdx.x & 31;
    int e0 = lane * 8;
    float inv[8];
    {
        float4 c0 = *(const float4*)&g_colsum[b * 256 + e0];
        float4 c1 = *(const float4*)&g_colsum[b * 256 + e0 + 4];
        inv[0] = __fdividef(1.f, c0.x + FEPS); inv[1] = __fdividef(1.f, c0.y + FEPS);
        inv[2] = __fdividef(1.f, c0.z + FEPS); inv[3] = __fdividef(1.f, c0.w + FEPS);
        inv[4] = __fdividef(1.f, c1.x + FEPS); inv[5] = __fdividef(1.f, c1.y + FEPS);
        inv[6] = __fdividef(1.f, c1.z + FEPS); inv[7] = __fdividef(1.f, c1.w + FEPS);
    }
    float ls[8] = {};
    for (int it = 0; it < 16; it++) {
        int n = chunk * 128 + it * 8 + wid;
        long base = ((long)b * SEQ + n) * 256 + e0;
        uint4 h = *(const uint4*)(g_pk_hi + base);
        uint4 l = *(const uint4*)(g_pk_lo + base);
        float4 v0 = *(const float4*)(V + base);
        float4 v1 = *(const float4*)(V + base + 4);
        uint32_t hu[4] = {h.x, h.y, h.z, h.w}, lu[4] = {l.x, l.y, l.z, l.w};
        float vv[8] = {v0.x, v0.y, v0.z, v0.w, v1.x, v1.y, v1.z, v1.w};
        float E[8];
#pragma unroll
        for (int p = 0; p < 4; p++) {
            float2 a = unpack_bf16(hu[p]), bb = unpack_bf16(lu[p]);
            E[2 * p]     = __expf((a.x + bb.x) * inv[2 * p] * vv[2 * p]);
            E[2 * p + 1] = __expf((a.y + bb.y) * inv[2 * p + 1] * vv[2 * p + 1]);
        }
        uint32_t ph[4], pl[4];
#pragma unroll
        for (int p = 0; p < 4; p++) {
            float a = E[2 * p], bb = E[2 * p + 1];
            ls[2 * p] += a; ls[2 * p + 1] += bb;
            ph[p] = pack_bf16(a, bb);
            pl[p] = pack_bf16(a - bf16_round(a), bb - bf16_round(bb));
        }
        *(uint4*)(g_E_hi + base) = make_uint4(ph[0], ph[1], ph[2], ph[3]);
        *(uint4*)(g_E_lo + base) = make_uint4(pl[0], pl[1], pl[2], pl[3]);
    }
#pragma unroll
    for (int j = 0; j < 8; j++) atomicAdd(&g_l[b * 256 + e0 + j], ls[j]);
}

// ---------------- KVs = split(KV / l[e]) ----------------
__global__ void kvscale_kernel() {
    long i = (long)blockIdx.x * 256 + threadIdx.x;
    int b = (int)(i >> 16), e = (int)(i & 255);
    float v = g_KV[i] * __fdividef(1.f, g_l[b * 256 + e]);
    g_KVs_hi[i] = __float2bfloat16(v);
    g_KVs_lo[i] = __float2bfloat16(v - bf16_round(v));
}

// ---------------- launch ----------------
extern "C" void kernel_launch(void* const* d_in, const int* in_sizes, int n_in,
                              void* d_out, int out_size) {
    const float* Q  = (const float*)d_in[0];
    const float* K  = (const float*)d_in[1];
    const float* V  = (const float*)d_in[2];
    const float* Wq = (const float*)d_in[3];
    const float* bq = (const float*)d_in[4];
    const float* Wk = (const float*)d_in[5];
    const float* bk = (const float*)d_in[6];
    float* out = (float*)d_out;

    cudaFuncSetAttribute(mgemm<0, 0>, cudaFuncAttributeMaxDynamicSharedMemorySize, SMEM_MG);
    cudaFuncSetAttribute(mgemm<2, 1>, cudaFuncAttributeMaxDynamicSharedMemorySize, SMEM_MG);
    cudaFuncSetAttribute(mgemm<1, 0>, cudaFuncAttributeMaxDynamicSharedMemorySize, SMEM_MG);

    void* p;
    cudaGetSymbolAddress(&p, g_KV);      float* KV = (float*)p;
    cudaGetSymbolAddress(&p, g_rowfac);  float* rowfac = (float*)p;
    cudaGetSymbolAddress(&p, g_Wq_hi);   __nv_bfloat16* Wq_hi = (__nv_bfloat16*)p;
    cudaGetSymbolAddress(&p, g_Wq_lo);   __nv_bfloat16* Wq_lo = (__nv_bfloat16*)p;
    cudaGetSymbolAddress(&p, g_Wk_hi);   __nv_bfloat16* Wk_hi = (__nv_bfloat16*)p;
    cudaGetSymbolAddress(&p, g_Wk_lo);   __nv_bfloat16* Wk_lo = (__nv_bfloat16*)p;
    cudaGetSymbolAddress(&p, g_Qs_hi);   __nv_bfloat16* Qs_hi = (__nv_bfloat16*)p;
    cudaGetSymbolAddress(&p, g_Qs_lo);   __nv_bfloat16* Qs_lo = (__nv_bfloat16*)p;
    cudaGetSymbolAddress(&p, g_Ks_hi);   __nv_bfloat16* Ks_hi = (__nv_bfloat16*)p;
    cudaGetSymbolAddress(&p, g_Ks_lo);   __nv_bfloat16* Ks_lo = (__nv_bfloat16*)p;
    cudaGetSymbolAddress(&p, g_pq_hi);   __nv_bfloat16* pq_hi = (__nv_bfloat16*)p;
    cudaGetSymbolAddress(&p, g_pq_lo);   __nv_bfloat16* pq_lo = (__nv_bfloat16*)p;
    cudaGetSymbolAddress(&p, g_pk_hi);   __nv_bfloat16* pk_hi = (__nv_bfloat16*)p;
    cudaGetSymbolAddress(&p, g_pk_lo);   __nv_bfloat16* pk_lo = (__nv_bfloat16*)p;
    cudaGetSymbolAddress(&p, g_E_hi);    __nv_bfloat16* E_hi = (__nv_bfloat16*)p;
    cudaGetSymbolAddress(&p, g_E_lo);    __nv_bfloat16* E_lo = (__nv_bfloat16*)p;
    cudaGetSymbolAddress(&p, g_KVs_hi);  __nv_bfloat16* KVs_hi = (__nv_bfloat16*)p;
    cudaGetSymbolAddress(&p, g_KVs_lo);  __nv_bfloat16* KVs_lo = (__nv_bfloat16*)p;

    zero_kernel<<<4096, 256>>>();
    wsplit_kernel<<<dim3(256, 2, 1), 256>>>(Wq, Wk);
    qksplit_kernel<<<dim3(BATCH * SEQ * DIM / 1024, 2, 1), 256>>>(Q, K);

    // phi_q / phi_k = sigmoid(X @ W + b), bf16 hi/lo out  (CTA covers full N=256)
    mgemm<0, 0><<<dim3(512, 1, 1), 256, SMEM_MG>>>(
        Qs_hi, Qs_lo, Wq_hi, Wq_lo, bq, nullptr, pq_hi, pq_lo, 8, 1, 0, 0, 0, 0);
    mgemm<0, 0><<<dim3(512, 1, 1), 256, SMEM_MG>>>(
        Ks_hi, Ks_lo, Wk_hi, Wk_lo, bk, nullptr, pk_hi, pk_lo, 8, 1, 0, 0, 0, 0);

    rowfac_kernel<<<BATCH * SEQ / 8, 256>>>();
    colsum_kernel<<<BATCH * 32, 256>>>();
    e_kernel<<<dim3(32, BATCH, 1), 256>>>(V);

    // KV[b] = phi_k^T @ E, K-split 8 + atomics
    mgemm<2, 1><<<dim3(2, 1, BATCH * 8), 256, SMEM_MG>>>(
        pk_hi, pk_lo, E_hi, E_lo, nullptr, KV, nullptr, nullptr,
        16, 8, 512, (long)SEQ * DIM, (long)SEQ * DIM, (long)DIM * DIM);

    kvscale_kernel<<<BATCH * DIM * DIM / 256, 256>>>();

    // R = rowfac * (phi_q @ KVs)
    mgemm<1, 0><<<dim3(32, 1, BATCH), 256, SMEM_MG>>>(
        pq_hi, pq_lo, KVs_hi, KVs_lo, rowfac, out, nullptr, nullptr,
        8, 1, 0, (long)SEQ * DIM, (long)DIM * DIM, (long)SEQ * DIM);
}